// round 3
// baseline (speedup 1.0000x reference)
#include <cuda_runtime.h>
#include <cuda_bf16.h>
#include <cstddef>

// Problem constants
#define T_STEPS 256
#define B_SZ    64
#define K_DIM   1024
#define H_DIM   1024
#define L_NUM   3
#define THREE_H 3072
#define M_ROWS  (T_STEPS * B_SZ)   // 16384

// ---------------------------------------------------------------------------
// Scratch (device globals — allocation-free per harness rules)
// ---------------------------------------------------------------------------
__device__ float g_gi [(size_t)M_ROWS * THREE_H];   // [T*B, 3H] gate-interleaved
__device__ float g_seq[(size_t)M_ROWS * H_DIM];     // [T, B, H] layer output
__device__ float g_h  [2][(size_t)B_SZ * H_DIM];    // ping-pong hidden state

// ---------------------------------------------------------------------------
// Kernel 1: gi = A @ Wih^T + b_ih, output columns gate-interleaved:
//   out col c  <->  j = c/3, gate = c%3, Wih row = gate*H + j
// A: [M, 1024] row-major (x for layer 0, g_seq for layers 1,2)
// ---------------------------------------------------------------------------
#define GM 64
#define GN 64
#define GK 32

__global__ __launch_bounds__(256) void gi_gemm_kernel(
    const float* __restrict__ A, const float* __restrict__ W,
    const float* __restrict__ bias, float* __restrict__ out)
{
    __shared__ float As[GK][GM + 4];
    __shared__ float Bs[GK][GN + 4];
    const int bm = blockIdx.y * GM;
    const int bn = blockIdx.x * GN;
    const int tid = threadIdx.x;
    const int tx = tid & 15, ty = tid >> 4;

    float acc[4][4] = {};

    for (int k0 = 0; k0 < K_DIM; k0 += GK) {
        // Load A tile (transposed into k-major smem)
        #pragma unroll
        for (int i = tid; i < GM * GK / 4; i += 256) {
            int m  = i >> 3;
            int kq = (i & 7) << 2;
            float4 v = *(const float4*)&A[(size_t)(bm + m) * K_DIM + k0 + kq];
            As[kq + 0][m] = v.x; As[kq + 1][m] = v.y;
            As[kq + 2][m] = v.z; As[kq + 3][m] = v.w;
        }
        // Load W tile (permuted rows, transposed into k-major smem)
        #pragma unroll
        for (int i = tid; i < GN * GK / 4; i += 256) {
            int n  = i >> 3;
            int kq = (i & 7) << 2;
            int c  = bn + n;
            int row = (c % 3) * H_DIM + (c / 3);
            float4 v = *(const float4*)&W[(size_t)row * K_DIM + k0 + kq];
            Bs[kq + 0][n] = v.x; Bs[kq + 1][n] = v.y;
            Bs[kq + 2][n] = v.z; Bs[kq + 3][n] = v.w;
        }
        __syncthreads();
        #pragma unroll
        for (int kk = 0; kk < GK; kk++) {
            float4 a = *(const float4*)&As[kk][ty * 4];
            float4 b = *(const float4*)&Bs[kk][tx * 4];
            acc[0][0] += a.x * b.x; acc[0][1] += a.x * b.y; acc[0][2] += a.x * b.z; acc[0][3] += a.x * b.w;
            acc[1][0] += a.y * b.x; acc[1][1] += a.y * b.y; acc[1][2] += a.y * b.z; acc[1][3] += a.y * b.w;
            acc[2][0] += a.z * b.x; acc[2][1] += a.z * b.y; acc[2][2] += a.z * b.z; acc[2][3] += a.z * b.w;
            acc[3][0] += a.w * b.x; acc[3][1] += a.w * b.y; acc[3][2] += a.w * b.z; acc[3][3] += a.w * b.w;
        }
        __syncthreads();
    }

    #pragma unroll
    for (int i = 0; i < 4; i++) {
        int m = bm + ty * 4 + i;
        #pragma unroll
        for (int j = 0; j < 4; j++) {
            int c = bn + tx * 4 + j;
            int row = (c % 3) * H_DIM + (c / 3);
            out[(size_t)m * THREE_H + c] = acc[i][j] + bias[row];
        }
    }
}

// ---------------------------------------------------------------------------
// Kernel 2: one GRU timestep, fused GEMM + gates.
// Block: jbase = blockIdx.x*8 (grid=128), 256 threads.
// In-block K split: tid>=128 accumulates k in [512,1024), reduced via smem.
// Thread (of 128): 4 b-rows x 1 j (3 gates).
// ---------------------------------------------------------------------------
#define SKC 32

__device__ __forceinline__ float sigm(float x) { return 1.0f / (1.0f + expf(-x)); }

__global__ __launch_bounds__(256) void gru_step_kernel(
    const float* __restrict__ gi_t,   // [B, 3H] interleaved
    const float* __restrict__ h_in,   // [B, H]
    const float* __restrict__ whh,    // [3H, H]
    const float* __restrict__ bhh,    // [3H]
    float* __restrict__ h_out,        // [B, H]
    float* __restrict__ out_t)        // [B, H] or nullptr
{
    __shared__ float h_s[2][SKC][B_SZ + 4];
    __shared__ float w_s[2][SKC][24];
    __shared__ float red_s[128][12];

    const int tid   = threadIdx.x;
    const int jbase = blockIdx.x * 8;
    const int g     = tid >> 7;        // k-half: 0 -> [0,512), 1 -> [512,1024)
    const int lt    = tid & 127;
    const int tb    = (lt & 15) * 4;   // base b row (4 rows)
    const int tc    = lt >> 4;         // j offset within tile, 0..7

    float acc[4][3] = {};

    for (int k0 = 0; k0 < 512; k0 += SKC) {
        // Load h chunks for both halves: 2 * 64 * 32 floats
        #pragma unroll
        for (int i = tid; i < 1024; i += 256) {
            int half = i >> 9;
            int r    = i & 511;
            int m    = r >> 3;
            int kq   = (r & 7) << 2;
            float4 v = *(const float4*)&h_in[(size_t)m * H_DIM + k0 + half * 512 + kq];
            h_s[half][kq + 0][m] = v.x; h_s[half][kq + 1][m] = v.y;
            h_s[half][kq + 2][m] = v.z; h_s[half][kq + 3][m] = v.w;
        }
        // Load w chunks (24 permuted rows) for both halves: 2 * 24 * 32 floats
        for (int i = tid; i < 384; i += 256) {
            int half = i / 192;
            int r    = i % 192;
            int c    = r >> 3;
            int kq   = (r & 7) << 2;
            int row  = (c % 3) * H_DIM + (jbase + c / 3);
            float4 v = *(const float4*)&whh[(size_t)row * H_DIM + k0 + half * 512 + kq];
            w_s[half][kq + 0][c] = v.x; w_s[half][kq + 1][c] = v.y;
            w_s[half][kq + 2][c] = v.z; w_s[half][kq + 3][c] = v.w;
        }
        __syncthreads();
        #pragma unroll
        for (int kk = 0; kk < SKC; kk++) {
            float4 hv = *(const float4*)&h_s[g][kk][tb];
            float w0 = w_s[g][kk][tc * 3 + 0];
            float w1 = w_s[g][kk][tc * 3 + 1];
            float w2 = w_s[g][kk][tc * 3 + 2];
            acc[0][0] += hv.x * w0; acc[0][1] += hv.x * w1; acc[0][2] += hv.x * w2;
            acc[1][0] += hv.y * w0; acc[1][1] += hv.y * w1; acc[1][2] += hv.y * w2;
            acc[2][0] += hv.z * w0; acc[2][1] += hv.z * w1; acc[2][2] += hv.z * w2;
            acc[3][0] += hv.w * w0; acc[3][1] += hv.w * w1; acc[3][2] += hv.w * w2;
        }
        __syncthreads();
    }

    // Reduce the two K halves
    if (g == 1) {
        #pragma unroll
        for (int i = 0; i < 4; i++)
            #pragma unroll
            for (int j = 0; j < 3; j++)
                red_s[lt][i * 3 + j] = acc[i][j];
    }
    __syncthreads();

    if (g == 0) {
        #pragma unroll
        for (int i = 0; i < 4; i++)
            #pragma unroll
            for (int j = 0; j < 3; j++)
                acc[i][j] += red_s[lt][i * 3 + j];

        const int j = jbase + tc;
        const float br = bhh[j];
        const float bz = bhh[H_DIM + j];
        const float bn = bhh[2 * H_DIM + j];

        #pragma unroll
        for (int i = 0; i < 4; i++) {
            int b = tb + i;
            const float* gp = gi_t + (size_t)b * THREE_H + j * 3;
            float r  = sigm(gp[0] + acc[i][0] + br);
            float z  = sigm(gp[1] + acc[i][1] + bz);
            float n  = tanhf(gp[2] + r * (acc[i][2] + bn));
            float hp = h_in[(size_t)b * H_DIM + j];
            float hn = (1.0f - z) * n + z * hp;
            h_out[(size_t)b * H_DIM + j] = hn;
            if (out_t) out_t[(size_t)b * H_DIM + j] = hn;
        }
    }
}

// ---------------------------------------------------------------------------
// Launch: per layer — one big gi GEMM, then 256 sequential fused step kernels.
// Stream order carries the recurrence; graph-capturable (kernels + D2D copies).
// ---------------------------------------------------------------------------
extern "C" void kernel_launch(void* const* d_in, const int* in_sizes, int n_in,
                              void* d_out, int out_size)
{
    (void)in_sizes; (void)n_in; (void)out_size;

    const float* x    = (const float*)d_in[0];
    const float* h0   = (const float*)d_in[1];
    const float* w_ih = (const float*)d_in[2];
    const float* w_hh = (const float*)d_in[3];
    const float* b_ih = (const float*)d_in[4];
    const float* b_hh = (const float*)d_in[5];
    float* out = (float*)d_out;

    float* gi  = nullptr;
    float* seq = nullptr;
    float* hb  = nullptr;
    cudaGetSymbolAddress((void**)&gi,  g_gi);
    cudaGetSymbolAddress((void**)&seq, g_seq);
    cudaGetSymbolAddress((void**)&hb,  g_h);

    const size_t BH = (size_t)B_SZ * H_DIM;   // 65536
    dim3 ggrid(THREE_H / GN, M_ROWS / GM);    // (48, 256)

    for (int l = 0; l < L_NUM; l++) {
        const float* A = (l == 0) ? x : seq;
        gi_gemm_kernel<<<ggrid, 256>>>(A,
                                       w_ih + (size_t)l * THREE_H * K_DIM,
                                       b_ih + (size_t)l * THREE_H,
                                       gi);
        cudaMemcpyAsync(hb, h0 + (size_t)l * BH, BH * sizeof(float),
                        cudaMemcpyDeviceToDevice, 0);
        for (int t = 0; t < T_STEPS; t++) {
            float* ot = (l < L_NUM - 1) ? (seq + (size_t)t * BH) : nullptr;
            gru_step_kernel<<<H_DIM / 8, 256>>>(
                gi + (size_t)t * B_SZ * THREE_H,
                hb + (size_t)(t & 1) * BH,
                w_hh + (size_t)l * THREE_H * H_DIM,
                b_hh + (size_t)l * THREE_H,
                hb + (size_t)((t + 1) & 1) * BH,
                ot);
        }
        // T even -> final hidden state is in buffer 0
        cudaMemcpyAsync(out + (size_t)l * BH, hb, BH * sizeof(float),
                        cudaMemcpyDeviceToDevice, 0);
    }
}

// round 4
// speedup vs baseline: 1.3330x; 1.3330x over previous
#include <cuda_runtime.h>
#include <cuda_bf16.h>
#include <cstddef>

// Problem constants
#define T_STEPS 256
#define B_SZ    64
#define K_DIM   1024
#define H_DIM   1024
#define L_NUM   3
#define THREE_H 3072
#define M_ROWS  (T_STEPS * B_SZ)   // 16384

// ---------------------------------------------------------------------------
// Scratch (device globals — allocation-free per harness rules)
// ---------------------------------------------------------------------------
__device__ float g_gi [(size_t)M_ROWS * THREE_H];   // [T*B, 3H] gate-interleaved
__device__ float g_seq[(size_t)M_ROWS * H_DIM];     // [T, B, H] layer output
__device__ float g_h  [2][(size_t)B_SZ * H_DIM];    // ping-pong hidden state

// ---------------------------------------------------------------------------
// Kernel 1: gi = A @ Wih^T + b_ih, output columns gate-interleaved:
//   out col c  <->  j = c/3, gate = c%3, Wih row = gate*H + j
// ---------------------------------------------------------------------------
#define GM 64
#define GN 64
#define GK 32

__global__ __launch_bounds__(256) void gi_gemm_kernel(
    const float* __restrict__ A, const float* __restrict__ W,
    const float* __restrict__ bias, float* __restrict__ out)
{
    __shared__ float As[GK][GM + 4];
    __shared__ float Bs[GK][GN + 4];
    const int bm = blockIdx.y * GM;
    const int bn = blockIdx.x * GN;
    const int tid = threadIdx.x;
    const int tx = tid & 15, ty = tid >> 4;

    float acc[4][4] = {};

    for (int k0 = 0; k0 < K_DIM; k0 += GK) {
        #pragma unroll
        for (int i = tid; i < GM * GK / 4; i += 256) {
            int m  = i >> 3;
            int kq = (i & 7) << 2;
            float4 v = *(const float4*)&A[(size_t)(bm + m) * K_DIM + k0 + kq];
            As[kq + 0][m] = v.x; As[kq + 1][m] = v.y;
            As[kq + 2][m] = v.z; As[kq + 3][m] = v.w;
        }
        #pragma unroll
        for (int i = tid; i < GN * GK / 4; i += 256) {
            int n  = i >> 3;
            int kq = (i & 7) << 2;
            int c  = bn + n;
            int row = (c % 3) * H_DIM + (c / 3);
            float4 v = *(const float4*)&W[(size_t)row * K_DIM + k0 + kq];
            Bs[kq + 0][n] = v.x; Bs[kq + 1][n] = v.y;
            Bs[kq + 2][n] = v.z; Bs[kq + 3][n] = v.w;
        }
        __syncthreads();
        #pragma unroll
        for (int kk = 0; kk < GK; kk++) {
            float4 a = *(const float4*)&As[kk][ty * 4];
            float4 b = *(const float4*)&Bs[kk][tx * 4];
            acc[0][0] += a.x * b.x; acc[0][1] += a.x * b.y; acc[0][2] += a.x * b.z; acc[0][3] += a.x * b.w;
            acc[1][0] += a.y * b.x; acc[1][1] += a.y * b.y; acc[1][2] += a.y * b.z; acc[1][3] += a.y * b.w;
            acc[2][0] += a.z * b.x; acc[2][1] += a.z * b.y; acc[2][2] += a.z * b.z; acc[2][3] += a.z * b.w;
            acc[3][0] += a.w * b.x; acc[3][1] += a.w * b.y; acc[3][2] += a.w * b.z; acc[3][3] += a.w * b.w;
        }
        __syncthreads();
    }

    #pragma unroll
    for (int i = 0; i < 4; i++) {
        int m = bm + ty * 4 + i;
        #pragma unroll
        for (int j = 0; j < 4; j++) {
            int c = bn + tx * 4 + j;
            int row = (c % 3) * H_DIM + (c / 3);
            out[(size_t)m * THREE_H + c] = acc[i][j] + bias[row];
        }
    }
}

// ---------------------------------------------------------------------------
// Kernel 2: one GRU timestep, fused GEMM + gates. Redesigned:
//  - 128 blocks x 256 threads; block owns 8 j's = 24 interleaved cols x 64 b.
//  - 16-way K split: group g = tid>>4 covers k in [g*64, (g+1)*64).
//  - thread tile: 16 b x 6 cols (2 j). 96 fp32 accumulators.
//  - smem k-contiguous (pad 12 floats), cp.async double-buffered staging.
//  - cross-group smem reduction, then 256-thread gate epilogue.
// ---------------------------------------------------------------------------
#define NG      16           // K-split groups
#define GK_STEP 64           // K per group
#define CH      8            // k per chunk (per group)
#define NCHUNK  (GK_STEP / CH)   // 8
#define KP      12           // padded k-dim in smem

// per-buffer float counts
#define HS_FLOATS (NG * B_SZ * KP)        // 12288
#define WS_FLOATS (NG * 24 * KP)          //  4608
#define BUF_FLOATS (HS_FLOATS + WS_FLOATS) // 16896
#define SMEM_DYN_BYTES (2 * BUF_FLOATS * 4) // 135168

__device__ __forceinline__ void cp16(float* dst_smem, const float* src) {
    unsigned sa = (unsigned)__cvta_generic_to_shared(dst_smem);
    asm volatile("cp.async.cg.shared.global [%0], [%1], 16;\n" :: "r"(sa), "l"(src));
}
__device__ __forceinline__ void cp_commit() {
    asm volatile("cp.async.commit_group;\n" ::: "memory");
}
template <int N>
__device__ __forceinline__ void cp_wait() {
    asm volatile("cp.async.wait_group %0;\n" :: "n"(N) : "memory");
}

__device__ __forceinline__ float sigm(float x) { return 1.0f / (1.0f + expf(-x)); }

__global__ __launch_bounds__(256, 1) void gru_step_kernel(
    const float* __restrict__ gi_t,   // [B, 3H] interleaved
    const float* __restrict__ h_in,   // [B, H]
    const float* __restrict__ whh,    // [3H, H]
    const float* __restrict__ bhh,    // [3H]
    float* __restrict__ h_out,        // [B, H]
    float* __restrict__ out_t)        // [B, H] or nullptr
{
    extern __shared__ float dyn[];

    const int tid    = threadIdx.x;
    const int jbase  = blockIdx.x * 8;        // global j base (8 j's / block)
    const int g      = tid >> 4;              // K-split group 0..15
    const int l16    = tid & 15;
    const int cb     = l16 & 3;               // col-quad: cols cb*6 .. cb*6+5
    const int bb     = l16 >> 2;              // b-quad:  b = bb*16 .. bb*16+15
    const int bbase  = bb * 16;
    const int cbase  = cb * 6;

    // smem accessors (k-contiguous, pad KP)
    //  h_s(buf,g,b,k) = dyn[buf*BUF + g*(64*KP) + b*KP + k]
    //  w_s(buf,g,c,k) = dyn[buf*BUF + HS + g*(24*KP) + c*KP + k]

    float acc[4][4][6];
    #pragma unroll
    for (int q = 0; q < 4; q++)
        #pragma unroll
        for (int i = 0; i < 4; i++)
            #pragma unroll
            for (int c = 0; c < 6; c++)
                acc[q][i][c] = 0.0f;

    // ---- staging lambda-ish (manual) ----
    // h: 2048 16B copies, w: 768 16B copies per chunk.
    #define STAGE(chn, buf)                                                        \
    {                                                                              \
        float* hb_ = dyn + (buf) * BUF_FLOATS;                                     \
        float* wb_ = hb_ + HS_FLOATS;                                              \
        _Pragma("unroll")                                                          \
        for (int i = tid; i < 2048; i += 256) {                                    \
            int kq = i & 1;                                                        \
            int b  = (i >> 1) & 63;                                                \
            int gg = i >> 7;                                                       \
            cp16(hb_ + gg * (B_SZ * KP) + b * KP + kq * 4,                         \
                 h_in + (size_t)b * H_DIM + gg * GK_STEP + (chn) * CH + kq * 4);   \
        }                                                                          \
        _Pragma("unroll")                                                          \
        for (int i = tid; i < 768; i += 256) {                                     \
            int kq = i & 1;                                                        \
            int c  = (i >> 1) % 24;                                                \
            int gg = i / 48;                                                       \
            int row = (c % 3) * H_DIM + (jbase + c / 3);                           \
            cp16(wb_ + gg * (24 * KP) + c * KP + kq * 4,                           \
                 whh + (size_t)row * H_DIM + gg * GK_STEP + (chn) * CH + kq * 4);  \
        }                                                                          \
        cp_commit();                                                               \
    }

    STAGE(0, 0);

    for (int ch = 0; ch < NCHUNK; ch++) {
        if (ch + 1 < NCHUNK) {
            STAGE(ch + 1, (ch + 1) & 1);
            cp_wait<1>();
        } else {
            cp_wait<0>();
        }
        __syncthreads();

        const float* hb = dyn + (ch & 1) * BUF_FLOATS + g * (B_SZ * KP);
        const float* wb = dyn + (ch & 1) * BUF_FLOATS + HS_FLOATS + g * (24 * KP);

        #pragma unroll
        for (int kk4 = 0; kk4 < CH; kk4 += 4) {
            float4 wv[6];
            #pragma unroll
            for (int c = 0; c < 6; c++)
                wv[c] = *(const float4*)&wb[(cbase + c) * KP + kk4];
            #pragma unroll
            for (int q = 0; q < 4; q++) {
                float4 hv[4];
                #pragma unroll
                for (int i = 0; i < 4; i++)
                    hv[i] = *(const float4*)&hb[(bbase + q * 4 + i) * KP + kk4];
                #pragma unroll
                for (int i = 0; i < 4; i++)
                    #pragma unroll
                    for (int c = 0; c < 6; c++) {
                        acc[q][i][c] += hv[i].x * wv[c].x;
                        acc[q][i][c] += hv[i].y * wv[c].y;
                        acc[q][i][c] += hv[i].z * wv[c].z;
                        acc[q][i][c] += hv[i].w * wv[c].w;
                    }
            }
        }
        __syncthreads();
    }

    // ---- cross-group reduction via smem (reuse staging buffers) ----
    // P[g][l16][i96], i96 = (b&15)*6 + (c%6) ; 16*16*96 floats = 96KB
    float* P = dyn;
    {
        float* mine = P + (g * 16 + l16) * 96;
        #pragma unroll
        for (int q = 0; q < 4; q++)
            #pragma unroll
            for (int i = 0; i < 4; i++) {
                // i96 base for b-local (q*4+i): (q*4+i)*6
                #pragma unroll
                for (int c = 0; c < 6; c++)
                    mine[(q * 4 + i) * 6 + c] = acc[q][i][c];
            }
    }
    __syncthreads();

    // ---- gate epilogue: 512 (b,j) units, 2 per thread ----
    #pragma unroll
    for (int uu = 0; uu < 2; uu++) {
        int u = tid + uu * 256;        // 0..511
        int b = u & 63;
        int j = u >> 6;                // 0..7 (local j)
        int l = (b >> 4) * 4 + (j >> 1);
        int ibase = (b & 15) * 6 + (j & 1) * 3;

        float s0 = 0.f, s1 = 0.f, s2 = 0.f;
        #pragma unroll
        for (int gg = 0; gg < NG; gg++) {
            const float* p = P + (gg * 16 + l) * 96 + ibase;
            s0 += p[0]; s1 += p[1]; s2 += p[2];
        }

        int jg = jbase + j;
        const float* gp = gi_t + (size_t)b * THREE_H + jg * 3;
        float r  = sigm(gp[0] + s0 + bhh[jg]);
        float z  = sigm(gp[1] + s1 + bhh[H_DIM + jg]);
        float n  = tanhf(gp[2] + r * (s2 + bhh[2 * H_DIM + jg]));
        float hp = h_in[(size_t)b * H_DIM + jg];
        float hn = (1.0f - z) * n + z * hp;
        h_out[(size_t)b * H_DIM + jg] = hn;
        if (out_t) out_t[(size_t)b * H_DIM + jg] = hn;
    }
}

// ---------------------------------------------------------------------------
// Launch
// ---------------------------------------------------------------------------
extern "C" void kernel_launch(void* const* d_in, const int* in_sizes, int n_in,
                              void* d_out, int out_size)
{
    (void)in_sizes; (void)n_in; (void)out_size;

    const float* x    = (const float*)d_in[0];
    const float* h0   = (const float*)d_in[1];
    const float* w_ih = (const float*)d_in[2];
    const float* w_hh = (const float*)d_in[3];
    const float* b_ih = (const float*)d_in[4];
    const float* b_hh = (const float*)d_in[5];
    float* out = (float*)d_out;

    float* gi  = nullptr;
    float* seq = nullptr;
    float* hb  = nullptr;
    cudaGetSymbolAddress((void**)&gi,  g_gi);
    cudaGetSymbolAddress((void**)&seq, g_seq);
    cudaGetSymbolAddress((void**)&hb,  g_h);

    cudaFuncSetAttribute(gru_step_kernel,
                         cudaFuncAttributeMaxDynamicSharedMemorySize,
                         SMEM_DYN_BYTES);

    const size_t BH = (size_t)B_SZ * H_DIM;   // 65536
    dim3 ggrid(THREE_H / GN, M_ROWS / GM);    // (48, 256)

    for (int l = 0; l < L_NUM; l++) {
        const float* A = (l == 0) ? x : seq;
        gi_gemm_kernel<<<ggrid, 256>>>(A,
                                       w_ih + (size_t)l * THREE_H * K_DIM,
                                       b_ih + (size_t)l * THREE_H,
                                       gi);
        cudaMemcpyAsync(hb, h0 + (size_t)l * BH, BH * sizeof(float),
                        cudaMemcpyDeviceToDevice, 0);
        for (int t = 0; t < T_STEPS; t++) {
            float* ot = (l < L_NUM - 1) ? (seq + (size_t)t * BH) : nullptr;
            gru_step_kernel<<<128, 256, SMEM_DYN_BYTES>>>(
                gi + (size_t)t * B_SZ * THREE_H,
                hb + (size_t)(t & 1) * BH,
                w_hh + (size_t)l * THREE_H * H_DIM,
                b_hh + (size_t)l * THREE_H,
                hb + (size_t)((t + 1) & 1) * BH,
                ot);
        }
        // T even -> final hidden state is in buffer 0
        cudaMemcpyAsync(out + (size_t)l * BH, hb, BH * sizeof(float),
                        cudaMemcpyDeviceToDevice, 0);
    }
}

// round 5
// speedup vs baseline: 1.6263x; 1.2201x over previous
#include <cuda_runtime.h>
#include <cuda_bf16.h>
#include <cstddef>

// Problem constants
#define T_STEPS 256
#define B_SZ    64
#define K_DIM   1024
#define H_DIM   1024
#define L_NUM   3
#define THREE_H 3072
#define M_ROWS  (T_STEPS * B_SZ)   // 16384
#define NBLK    128

typedef unsigned long long ull;

// ---------------------------------------------------------------------------
// Scratch (device globals — allocation-free per harness rules)
// ---------------------------------------------------------------------------
__device__ float  g_gi  [(size_t)M_ROWS * THREE_H];      // [T*B, 3H] gate-interleaved
__device__ float  g_seq [(size_t)M_ROWS * H_DIM];        // [T, B, H] layer output
__device__ float2 g_hdup[2][(size_t)H_DIM * B_SZ];       // ping-pong h, duplicated: [k][b]=(h,h)
__device__ unsigned g_bar_cnt = 0;
__device__ unsigned g_bar_gen = 0;

// ---------------------------------------------------------------------------
// Kernel 1: gi = A @ Wih^T + b_ih, output columns gate-interleaved:
//   out col c  <->  j = c/3, gate = c%3, Wih row = gate*H + j
// ---------------------------------------------------------------------------
#define GM 64
#define GN 64
#define GK 32

__global__ __launch_bounds__(256) void gi_gemm_kernel(
    const float* __restrict__ A, const float* __restrict__ W,
    const float* __restrict__ bias, float* __restrict__ out)
{
    __shared__ float As[GK][GM + 4];
    __shared__ float Bs[GK][GN + 4];
    const int bm = blockIdx.y * GM;
    const int bn = blockIdx.x * GN;
    const int tid = threadIdx.x;
    const int tx = tid & 15, ty = tid >> 4;

    float acc[4][4] = {};

    for (int k0 = 0; k0 < K_DIM; k0 += GK) {
        #pragma unroll
        for (int i = tid; i < GM * GK / 4; i += 256) {
            int m  = i >> 3;
            int kq = (i & 7) << 2;
            float4 v = *(const float4*)&A[(size_t)(bm + m) * K_DIM + k0 + kq];
            As[kq + 0][m] = v.x; As[kq + 1][m] = v.y;
            As[kq + 2][m] = v.z; As[kq + 3][m] = v.w;
        }
        #pragma unroll
        for (int i = tid; i < GN * GK / 4; i += 256) {
            int n  = i >> 3;
            int kq = (i & 7) << 2;
            int c  = bn + n;
            int row = (c % 3) * H_DIM + (c / 3);
            float4 v = *(const float4*)&W[(size_t)row * K_DIM + k0 + kq];
            Bs[kq + 0][n] = v.x; Bs[kq + 1][n] = v.y;
            Bs[kq + 2][n] = v.z; Bs[kq + 3][n] = v.w;
        }
        __syncthreads();
        #pragma unroll
        for (int kk = 0; kk < GK; kk++) {
            float4 a = *(const float4*)&As[kk][ty * 4];
            float4 b = *(const float4*)&Bs[kk][tx * 4];
            acc[0][0] += a.x * b.x; acc[0][1] += a.x * b.y; acc[0][2] += a.x * b.z; acc[0][3] += a.x * b.w;
            acc[1][0] += a.y * b.x; acc[1][1] += a.y * b.y; acc[1][2] += a.y * b.z; acc[1][3] += a.y * b.w;
            acc[2][0] += a.z * b.x; acc[2][1] += a.z * b.y; acc[2][2] += a.z * b.z; acc[2][3] += a.z * b.w;
            acc[3][0] += a.w * b.x; acc[3][1] += a.w * b.y; acc[3][2] += a.w * b.z; acc[3][3] += a.w * b.w;
        }
        __syncthreads();
    }

    #pragma unroll
    for (int i = 0; i < 4; i++) {
        int m = bm + ty * 4 + i;
        #pragma unroll
        for (int j = 0; j < 4; j++) {
            int c = bn + tx * 4 + j;
            int row = (c % 3) * H_DIM + (c / 3);
            out[(size_t)m * THREE_H + c] = acc[i][j] + bias[row];
        }
    }
}

// ---------------------------------------------------------------------------
// dup_init: hdup[0][k][b] = (h0[b][k], h0[b][k])
// ---------------------------------------------------------------------------
__global__ __launch_bounds__(256) void dup_init_kernel(
    const float* __restrict__ h0l, float2* __restrict__ hdup0)
{
    int i = blockIdx.x * 256 + threadIdx.x;   // 0..65535
    int b = i >> 10, k = i & 1023;
    float v = h0l[b * H_DIM + k];
    hdup0[k * B_SZ + b] = make_float2(v, v);
}

// ---------------------------------------------------------------------------
// Persistent GRU recurrence kernel.
//  - 128 blocks x 256 threads, 1 block/SM, Whh slice (24 cols x 1024 k, 96KB)
//    resident in smem across all 256 timesteps.
//  - 4-way K-split (group g = tid>>6 covers k in [g*256,(g+1)*256)).
//  - thread tile: 4 b x 3 col-pairs, f32x2 packed accumulators (fma.rn.f32x2).
//  - h staged per 32-k chunk via cp.async from duplicated global buffer,
//    double-buffered.
//  - software grid barrier between timesteps.
// ---------------------------------------------------------------------------
#define WSM_FLOATS 24576                        // 1024 * 24
#define HD_F2      16384                        // 2 buf * 4 g * 32 kk * 64 b
#define DYN_BYTES  (WSM_FLOATS * 4 + HD_F2 * 8) // 98304 + 131072 = 229376

__device__ __forceinline__ void fma2(ull& d, ull a, ull b) {
    asm("fma.rn.f32x2 %0, %1, %2, %0;" : "+l"(d) : "l"(a), "l"(b));
}
__device__ __forceinline__ float2 u2f(ull v) {
    float2 f;
    f.x = __uint_as_float((unsigned)v);
    f.y = __uint_as_float((unsigned)(v >> 32));
    return f;
}
__device__ __forceinline__ void cp16(void* dst, const void* src) {
    unsigned sa = (unsigned)__cvta_generic_to_shared(dst);
    asm volatile("cp.async.cg.shared.global [%0], [%1], 16;" :: "r"(sa), "l"(src));
}
__device__ __forceinline__ void cp_commit() {
    asm volatile("cp.async.commit_group;" ::: "memory");
}
template <int N>
__device__ __forceinline__ void cp_wait() {
    asm volatile("cp.async.wait_group %0;" :: "n"(N) : "memory");
}
__device__ __forceinline__ float sigm(float x) { return 1.0f / (1.0f + expf(-x)); }

__device__ __forceinline__ void grid_sync_() {
    __syncthreads();
    if (threadIdx.x == 0) {
        __threadfence();
        unsigned gen = *(volatile unsigned*)&g_bar_gen;
        unsigned ticket = atomicAdd(&g_bar_cnt, 1u);
        if (ticket == NBLK - 1) {
            g_bar_cnt = 0;
            __threadfence();
            atomicAdd(&g_bar_gen, 1u);
        } else {
            while (*(volatile unsigned*)&g_bar_gen == gen) __nanosleep(32);
        }
    }
    __syncthreads();
}

__device__ __forceinline__ void stage_chunk(
    float2* hd, const float2* hin, int g, int lt, int ch, int buf)
{
    const float2* src = hin + (size_t)(g * 256 + ch * 32) * B_SZ;
    float2* dst = hd + (buf * 4 + g) * 2048;
    #pragma unroll
    for (int i = 0; i < 16; i++) {
        int c16 = i * 64 + lt;           // 16B-chunk index, 0..1023
        cp16(dst + c16 * 2, src + c16 * 2);
    }
}

__global__ __launch_bounds__(256, 1) void gru_persistent_kernel(
    const float* __restrict__ gi,     // [T, B, 3H] interleaved
    float2* __restrict__ hdup,        // [2][1024][64] dup h (ping-pong)
    const float* __restrict__ whh,    // [3H, H]
    const float* __restrict__ bhh,    // [3H]
    float* __restrict__ seq_out,      // [T, B, H] or nullptr
    float* __restrict__ hlast)        // [B, H] final hidden
{
    extern __shared__ float dyn[];
    float*  wsm = dyn;                         // [1024][24]
    float2* hd  = (float2*)(dyn + WSM_FLOATS); // [2][4][32][64]

    const int tid   = threadIdx.x;
    const int jbase = blockIdx.x * 8;
    const int g     = tid >> 6;        // K group 0..3
    const int lt    = tid & 63;
    const int bbase = (lt >> 2) * 4;   // 4 b rows
    const int cc    = lt & 3;          // col quad: cols cc*6..cc*6+5 (3 pairs)

    // Load Whh slice (permuted, k-major rows of 24 cols)
    for (int idx = tid; idx < WSM_FLOATS; idx += 256) {
        int c = idx >> 10, k = idx & 1023;
        int row = (c % 3) * H_DIM + (jbase + c / 3);
        wsm[k * 24 + c] = whh[(size_t)row * H_DIM + k];
    }
    // Epilogue constants: both units share j = tid&7
    const int ep_j  = tid & 7;
    const int ep_jg = jbase + ep_j;
    const float br = bhh[ep_jg];
    const float bz = bhh[H_DIM + ep_jg];
    const float bn = bhh[2 * H_DIM + ep_jg];
    __syncthreads();

    const bool wr_seq = (seq_out != nullptr);

    for (int t = 0; t < T_STEPS; t++) {
        const float2* hin  = hdup + (size_t)(t & 1) * (H_DIM * B_SZ);
        float2*       hout = hdup + (size_t)((t + 1) & 1) * (H_DIM * B_SZ);
        const float*  gi_t = gi + (size_t)t * B_SZ * THREE_H;

        grid_sync_();   // h from previous step visible; smem safe to overwrite

        ull acc[4][3];
        #pragma unroll
        for (int i = 0; i < 4; i++)
            #pragma unroll
            for (int p = 0; p < 3; p++)
                acc[i][p] = 0ull;

        stage_chunk(hd, hin, g, lt, 0, 0);
        cp_commit();

        for (int ch = 0; ch < 8; ch++) {
            if (ch < 7) {
                stage_chunk(hd, hin, g, lt, ch + 1, (ch + 1) & 1);
                cp_commit();
                cp_wait<1>();
            } else {
                cp_wait<0>();
            }
            __syncthreads();

            const float2* hrow = hd + ((ch & 1) * 4 + g) * 2048;
            const float*  wbase = wsm + (g * 256 + ch * 32) * 24 + cc * 6;
            #pragma unroll 4
            for (int kk = 0; kk < 32; kk++) {
                const float* wr = wbase + kk * 24;
                ull w0 = *(const ull*)(wr);
                ull w1 = *(const ull*)(wr + 2);
                ull w2 = *(const ull*)(wr + 4);
                const ulonglong2* hp2 = (const ulonglong2*)(hrow + kk * 64 + bbase);
                ulonglong2 h01 = hp2[0];
                ulonglong2 h23 = hp2[1];
                fma2(acc[0][0], h01.x, w0); fma2(acc[0][1], h01.x, w1); fma2(acc[0][2], h01.x, w2);
                fma2(acc[1][0], h01.y, w0); fma2(acc[1][1], h01.y, w1); fma2(acc[1][2], h01.y, w2);
                fma2(acc[2][0], h23.x, w0); fma2(acc[2][1], h23.x, w1); fma2(acc[2][2], h23.x, w2);
                fma2(acc[3][0], h23.y, w0); fma2(acc[3][1], h23.y, w1); fma2(acc[3][2], h23.y, w2);
            }
            __syncthreads();
        }

        // Cross-group reduction via smem (overlay on hd buffer 0)
        ull* red = (ull*)(dyn + WSM_FLOATS);   // [4*64][12]
        {
            ull* mine = red + (g * 64 + lt) * 12;
            #pragma unroll
            for (int i = 0; i < 4; i++)
                #pragma unroll
                for (int p = 0; p < 3; p++)
                    mine[i * 3 + p] = acc[i][p];
        }
        __syncthreads();

        // Gate epilogue: 512 (b,j) units, 2 per thread (j fast for coalesced gi)
        #pragma unroll
        for (int uu = 0; uu < 2; uu++) {
            int u = tid + uu * 256;
            int b = u >> 3;                    // j = u & 7 == ep_j
            float s[3];
            #pragma unroll
            for (int gt = 0; gt < 3; gt++) {
                int c   = ep_j * 3 + gt;       // 0..23
                int P   = c >> 1;
                int ln  = c & 1;
                int ltp = (b >> 2) * 4 + P / 3;
                int idx = (b & 3) * 3 + (P % 3);
                float acc_s = 0.f;
                #pragma unroll
                for (int gg = 0; gg < 4; gg++) {
                    float2 f = u2f(red[(gg * 64 + ltp) * 12 + idx]);
                    acc_s += ln ? f.y : f.x;
                }
                s[gt] = acc_s;
            }
            const float* gp = gi_t + (size_t)b * THREE_H + ep_jg * 3;
            float r  = sigm(gp[0] + s[0] + br);
            float z  = sigm(gp[1] + s[1] + bz);
            float n  = tanhf(gp[2] + r * (s[2] + bn));
            float hp = __ldcg((const float*)&hin[ep_jg * B_SZ + b]);
            float hn = (1.0f - z) * n + z * hp;
            hout[ep_jg * B_SZ + b] = make_float2(hn, hn);
            if (wr_seq)
                seq_out[(size_t)t * (B_SZ * H_DIM) + (size_t)b * H_DIM + ep_jg] = hn;
            if (t == T_STEPS - 1)
                hlast[(size_t)b * H_DIM + ep_jg] = hn;
        }
    }
}

// ---------------------------------------------------------------------------
// Launch: per layer — gi GEMM, h0 dup init, one persistent recurrence kernel.
// ---------------------------------------------------------------------------
extern "C" void kernel_launch(void* const* d_in, const int* in_sizes, int n_in,
                              void* d_out, int out_size)
{
    (void)in_sizes; (void)n_in; (void)out_size;

    const float* x    = (const float*)d_in[0];
    const float* h0   = (const float*)d_in[1];
    const float* w_ih = (const float*)d_in[2];
    const float* w_hh = (const float*)d_in[3];
    const float* b_ih = (const float*)d_in[4];
    const float* b_hh = (const float*)d_in[5];
    float* out = (float*)d_out;

    float*  gi   = nullptr;
    float*  seq  = nullptr;
    float2* hdup = nullptr;
    cudaGetSymbolAddress((void**)&gi,   g_gi);
    cudaGetSymbolAddress((void**)&seq,  g_seq);
    cudaGetSymbolAddress((void**)&hdup, g_hdup);

    cudaFuncSetAttribute(gru_persistent_kernel,
                         cudaFuncAttributeMaxDynamicSharedMemorySize,
                         DYN_BYTES);

    const size_t BH = (size_t)B_SZ * H_DIM;   // 65536
    dim3 ggrid(THREE_H / GN, M_ROWS / GM);    // (48, 256)

    for (int l = 0; l < L_NUM; l++) {
        const float* A = (l == 0) ? x : seq;
        gi_gemm_kernel<<<ggrid, 256>>>(A,
                                       w_ih + (size_t)l * THREE_H * K_DIM,
                                       b_ih + (size_t)l * THREE_H,
                                       gi);
        dup_init_kernel<<<256, 256>>>(h0 + (size_t)l * BH, hdup);
        gru_persistent_kernel<<<NBLK, 256, DYN_BYTES>>>(
            gi, hdup,
            w_hh + (size_t)l * THREE_H * H_DIM,
            b_hh + (size_t)l * THREE_H,
            (l < L_NUM - 1) ? seq : nullptr,
            out + (size_t)l * BH);
    }
}

// round 6
// speedup vs baseline: 1.7403x; 1.0701x over previous
#include <cuda_runtime.h>
#include <cuda_bf16.h>
#include <cstddef>

// Problem constants
#define T_STEPS 256
#define B_SZ    64
#define K_DIM   1024
#define H_DIM   1024
#define L_NUM   3
#define THREE_H 3072
#define M_ROWS  16384
#define NBLK    128

typedef unsigned long long ull;

// ---------------------------------------------------------------------------
// Scratch (device globals — allocation-free per harness rules)
// ---------------------------------------------------------------------------
__device__ float g_gi [(size_t)M_ROWS * THREE_H];   // [T*B, 3H] gate-interleaved
__device__ float g_seq[(size_t)M_ROWS * H_DIM];     // [T, B, H] layer output
__device__ float g_hp [2][(size_t)H_DIM * B_SZ];    // ping-pong h, plain [k][b]
__device__ unsigned g_bar_cnt = 0;
__device__ unsigned g_bar_gen = 0;

// ---------------------------------------------------------------------------
// f32x2 helpers
// ---------------------------------------------------------------------------
__device__ __forceinline__ void fma2(ull& d, ull a, ull b) {
    asm("fma.rn.f32x2 %0, %1, %2, %0;" : "+l"(d) : "l"(a), "l"(b));
}
__device__ __forceinline__ ull add2(ull a, ull b) {
    ull r;
    asm("add.rn.f32x2 %0, %1, %2;" : "=l"(r) : "l"(a), "l"(b));
    return r;
}
__device__ __forceinline__ ull dup2(float x) {
    ull r;
    unsigned u = __float_as_uint(x);
    asm("mov.b64 %0, {%1,%1};" : "=l"(r) : "r"(u));
    return r;
}
__device__ __forceinline__ void cp16(void* dst, const void* src) {
    unsigned sa = (unsigned)__cvta_generic_to_shared(dst);
    asm volatile("cp.async.cg.shared.global [%0], [%1], 16;" :: "r"(sa), "l"(src));
}
__device__ __forceinline__ void cp_commit() {
    asm volatile("cp.async.commit_group;" ::: "memory");
}
template <int N>
__device__ __forceinline__ void cp_wait() {
    asm volatile("cp.async.wait_group %0;" :: "n"(N) : "memory");
}
__device__ __forceinline__ float sigm(float x) { return 1.0f / (1.0f + expf(-x)); }

// ---------------------------------------------------------------------------
// Kernel 1: gi = A @ Wih^T + b_ih (cols gate-interleaved c = j*3+gate).
// f32x2: lanes = adjacent output-column pairs. A duplicated in smem, B plain.
// BM=128, BN=128, BK=16, 256 threads, thread tile 8m x 8n (4 n-pairs).
// ---------------------------------------------------------------------------
#define BM 128
#define BN 128
#define BK 16
#define NIT (K_DIM / BK)    // 64

__global__ __launch_bounds__(256, 2) void gi_gemm_kernel(
    const float* __restrict__ A, const float* __restrict__ W,
    const float* __restrict__ bias, float* __restrict__ out)
{
    __shared__ float2 As[2][BK * 128];   // [k][m] duplicated (a,a)  32KB
    __shared__ float  Bs[2][BK * 128];   // [k][n] plain             16KB

    const int tid = threadIdx.x;
    const int tx  = tid & 15;            // n-group: nbase = tx*8
    const int ty  = tid >> 4;            // m-group: mbase = ty*8
    const int bm  = blockIdx.y * BM;
    const int bn  = blockIdx.x * BN;

    // staging: thread t loads 8 floats of A (m=t>>1, k8=(t&1)*8) and of B
    const int sm_ = tid >> 1;
    const int sk8 = (tid & 1) * 8;
    const float* aptr = A + (size_t)(bm + sm_) * K_DIM + sk8;
    const int    cB   = bn + sm_;
    const float* bptr = W + (size_t)((cB % 3) * H_DIM + cB / 3) * K_DIM + sk8;

    // bias pairs for this thread's 8 columns
    ull biasp[4];
    #pragma unroll
    for (int p = 0; p < 4; p++) {
        int c0 = bn + tx * 8 + 2 * p;
        float blo = bias[(c0 % 3) * H_DIM + c0 / 3];
        float bhi = bias[((c0 + 1) % 3) * H_DIM + (c0 + 1) / 3];
        float2 bp = make_float2(blo, bhi);
        biasp[p] = *(ull*)&bp;
    }

    ull acc[8][4];
    #pragma unroll
    for (int m = 0; m < 8; m++)
        #pragma unroll
        for (int p = 0; p < 4; p++)
            acc[m][p] = 0ull;

    // prefetch tile 0
    float4 ra0 = *(const float4*)(aptr);
    float4 ra1 = *(const float4*)(aptr + 4);
    float4 rb0 = *(const float4*)(bptr);
    float4 rb1 = *(const float4*)(bptr + 4);
    {
        float a[8] = {ra0.x, ra0.y, ra0.z, ra0.w, ra1.x, ra1.y, ra1.z, ra1.w};
        float b[8] = {rb0.x, rb0.y, rb0.z, rb0.w, rb1.x, rb1.y, rb1.z, rb1.w};
        #pragma unroll
        for (int j = 0; j < 8; j++) {
            As[0][(sk8 + j) * 128 + sm_] = make_float2(a[j], a[j]);
            Bs[0][(sk8 + j) * 128 + sm_] = b[j];
        }
    }
    __syncthreads();

    for (int it = 0; it < NIT; it++) {
        const int cur = it & 1;
        if (it + 1 < NIT) {
            const float* ap = aptr + (it + 1) * BK;
            const float* bp = bptr + (it + 1) * BK;
            ra0 = *(const float4*)(ap);
            ra1 = *(const float4*)(ap + 4);
            rb0 = *(const float4*)(bp);
            rb1 = *(const float4*)(bp + 4);
        }
        #pragma unroll
        for (int k = 0; k < BK; k++) {
            const ulonglong2* ar = (const ulonglong2*)&As[cur][k * 128 + ty * 8];
            const ulonglong2* br = (const ulonglong2*)&Bs[cur][k * 128 + tx * 8];
            ulonglong2 a01 = ar[0], a23 = ar[1], a45 = ar[2], a67 = ar[3];
            ulonglong2 b01 = br[0], b23 = br[1];
            ull av[8] = {a01.x, a01.y, a23.x, a23.y, a45.x, a45.y, a67.x, a67.y};
            ull bv[4] = {b01.x, b01.y, b23.x, b23.y};
            #pragma unroll
            for (int m = 0; m < 8; m++)
                #pragma unroll
                for (int p = 0; p < 4; p++)
                    fma2(acc[m][p], av[m], bv[p]);
        }
        if (it + 1 < NIT) {
            const int nxt = cur ^ 1;
            float a[8] = {ra0.x, ra0.y, ra0.z, ra0.w, ra1.x, ra1.y, ra1.z, ra1.w};
            float b[8] = {rb0.x, rb0.y, rb0.z, rb0.w, rb1.x, rb1.y, rb1.z, rb1.w};
            #pragma unroll
            for (int j = 0; j < 8; j++) {
                As[nxt][(sk8 + j) * 128 + sm_] = make_float2(a[j], a[j]);
                Bs[nxt][(sk8 + j) * 128 + sm_] = b[j];
            }
        }
        __syncthreads();
    }

    #pragma unroll
    for (int m = 0; m < 8; m++) {
        float* orow = out + (size_t)(bm + ty * 8 + m) * THREE_H + bn + tx * 8;
        #pragma unroll
        for (int p = 0; p < 4; p++)
            ((ull*)orow)[p] = add2(acc[m][p], biasp[p]);
    }
}

// ---------------------------------------------------------------------------
// h_init: h[k][b] = h0l[b][k]
// ---------------------------------------------------------------------------
__global__ __launch_bounds__(256) void h_init_kernel(
    const float* __restrict__ h0l, float* __restrict__ hdst)
{
    int i = blockIdx.x * 256 + threadIdx.x;   // 0..65535
    int k = i >> 6, b = i & 63;
    hdst[i] = h0l[b * H_DIM + k];
}

// ---------------------------------------------------------------------------
// Persistent GRU recurrence.
//  - 128 blocks x 256 thr, 1 block/SM. Whh slice (24 cols x 1024, 96KB) in smem.
//  - h plain [k][b]; f32x2 lanes = b-pairs (natural LDS.128 h fragments).
//  - 16-way K split (g=tid>>4, k = ch*256 + q*64 + g*4 + r), thread tile
//    16b(8 pairs) x 6 cols -> 48 FFMA2/k, w dup'd via MOV.
//  - 4 chunks of 256 k staged via cp.async, double-buffered (2x64KB).
//  - partials (256 thr x 48 ull) overlaid on h buffers, 256-thr gate epilogue.
// ---------------------------------------------------------------------------
#define WSM_FLOATS  24576                    // 1024 * 24
#define HBUF_FLOATS 16384                    // 256 k * 64 b
#define RDYN_BYTES  ((WSM_FLOATS + 2 * HBUF_FLOATS) * 4)   // 229376

__device__ __forceinline__ void grid_sync_() {
    __threadfence();
    __syncthreads();
    if (threadIdx.x == 0) {
        unsigned gen = *(volatile unsigned*)&g_bar_gen;
        unsigned ticket = atomicAdd(&g_bar_cnt, 1u);
        if (ticket == NBLK - 1) {
            g_bar_cnt = 0;
            __threadfence();
            atomicAdd(&g_bar_gen, 1u);
        } else {
            while (*(volatile unsigned*)&g_bar_gen == gen) __nanosleep(32);
        }
    }
    __syncthreads();
}

__device__ __forceinline__ void stage_chunk(
    float* hbuf, const float* hin, int tid, int ch, int buf)
{
    const float* src = hin + ch * HBUF_FLOATS;
    float* dst = hbuf + buf * HBUF_FLOATS;
    #pragma unroll
    for (int i = 0; i < 16; i++) {
        int o = (i * 256 + tid) * 4;
        cp16(dst + o, src + o);
    }
}

__global__ __launch_bounds__(256, 1) void gru_persistent_kernel(
    const float* __restrict__ gi,     // [T, B, 3H] interleaved
    float* __restrict__ h,            // [2][1024][64] plain
    const float* __restrict__ whh,    // [3H, H]
    const float* __restrict__ bhh,    // [3H]
    float* __restrict__ seq_out,      // [T, B, H] or nullptr
    float* __restrict__ hlast)        // [B, H]
{
    extern __shared__ float dyn[];
    float* wsm  = dyn;                 // [1024][24]
    float* hbuf = dyn + WSM_FLOATS;    // [2][256][64]

    const int tid   = threadIdx.x;
    const int jbase = blockIdx.x * 8;
    const int g     = tid >> 4;        // 0..15
    const int lt    = tid & 15;
    const int bbase = (lt >> 2) * 16;  // 16 b rows (8 pairs)
    const int cbase = (lt & 3) * 6;    // 6 cols

    for (int idx = tid; idx < WSM_FLOATS; idx += 256) {
        int c = idx >> 10, k = idx & 1023;
        int row = (c % 3) * H_DIM + (jbase + c / 3);
        wsm[k * 24 + c] = whh[(size_t)row * H_DIM + k];
    }
    const int ep_j  = tid & 7;
    const int ep_jg = jbase + ep_j;
    const float br  = bhh[ep_jg];
    const float bz  = bhh[H_DIM + ep_jg];
    const float bn_ = bhh[2 * H_DIM + ep_jg];
    __syncthreads();

    const bool wr_seq = (seq_out != nullptr);

    for (int t = 0; t < T_STEPS; t++) {
        const float* hin  = h + (size_t)(t & 1) * (H_DIM * B_SZ);
        float*       hout = h + (size_t)((t + 1) & 1) * (H_DIM * B_SZ);
        const float* gi_t = gi + (size_t)t * B_SZ * THREE_H;

        grid_sync_();   // prev-step h visible; smem (incl. red overlay) free

        ull acc[8][6];
        #pragma unroll
        for (int p = 0; p < 8; p++)
            #pragma unroll
            for (int c = 0; c < 6; c++)
                acc[p][c] = 0ull;

        stage_chunk(hbuf, hin, tid, 0, 0);
        cp_commit();

        for (int ch = 0; ch < 4; ch++) {
            if (ch < 3) {
                stage_chunk(hbuf, hin, tid, ch + 1, (ch + 1) & 1);
                cp_commit();
                cp_wait<1>();
            } else {
                cp_wait<0>();
            }
            __syncthreads();

            const float* hb = hbuf + (ch & 1) * HBUF_FLOATS;
            #pragma unroll
            for (int q = 0; q < 4; q++) {
                #pragma unroll
                for (int r = 0; r < 4; r++) {
                    const int klocal = q * 64 + g * 4 + r;
                    const int kglob  = (ch << 8) + klocal;
                    const float* wr_ = wsm + kglob * 24 + cbase;
                    float2 w01 = *(const float2*)(wr_);
                    float2 w23 = *(const float2*)(wr_ + 2);
                    float2 w45 = *(const float2*)(wr_ + 4);
                    ull wd0 = dup2(w01.x), wd1 = dup2(w01.y);
                    ull wd2 = dup2(w23.x), wd3 = dup2(w23.y);
                    ull wd4 = dup2(w45.x), wd5 = dup2(w45.y);
                    const ulonglong2* hp_ =
                        (const ulonglong2*)(hb + klocal * 64 + bbase);
                    ulonglong2 h01 = hp_[0], h23 = hp_[1];
                    ulonglong2 h45 = hp_[2], h67 = hp_[3];
                    ull hv[8] = {h01.x, h01.y, h23.x, h23.y,
                                 h45.x, h45.y, h67.x, h67.y};
                    #pragma unroll
                    for (int p = 0; p < 8; p++) {
                        fma2(acc[p][0], hv[p], wd0);
                        fma2(acc[p][1], hv[p], wd1);
                        fma2(acc[p][2], hv[p], wd2);
                        fma2(acc[p][3], hv[p], wd3);
                        fma2(acc[p][4], hv[p], wd4);
                        fma2(acc[p][5], hv[p], wd5);
                    }
                }
            }
            __syncthreads();
        }

        // partials: red[(g*16+lt)][p*6+c] = red[tid][...]
        ull* red = (ull*)(dyn + WSM_FLOATS);
        {
            ull* mine = red + tid * 48;
            #pragma unroll
            for (int p = 0; p < 8; p++)
                #pragma unroll
                for (int c = 0; c < 6; c++)
                    mine[p * 6 + c] = acc[p][c];
        }
        __syncthreads();

        // gate epilogue: 512 (b,j) units, 2 per thread
        #pragma unroll
        for (int uu = 0; uu < 2; uu++) {
            int u  = tid + uu * 256;
            int b  = u >> 3;                 // j = u&7 == ep_j
            int bq = b >> 4;
            int p_ = (b & 15) >> 1;
            int ln = b & 1;
            float s[3];
            #pragma unroll
            for (int gt = 0; gt < 3; gt++) {
                int cg  = ep_j * 3 + gt;     // 0..23
                int ltp = bq * 4 + cg / 6;
                int idx = p_ * 6 + (cg % 6);
                float acc_s = 0.f;
                #pragma unroll
                for (int gg = 0; gg < 16; gg++) {
                    ull v = red[(gg * 16 + ltp) * 48 + idx];
                    float2 f = *(float2*)&v;
                    acc_s += ln ? f.y : f.x;
                }
                s[gt] = acc_s;
            }
            const float* gp = gi_t + (size_t)b * THREE_H + ep_jg * 3;
            float r  = sigm(gp[0] + s[0] + br);
            float z  = sigm(gp[1] + s[1] + bz);
            float n  = tanhf(gp[2] + r * (s[2] + bn_));
            float hp = __ldcg(hin + ep_jg * 64 + b);
            float hn = (1.0f - z) * n + z * hp;
            hout[ep_jg * 64 + b] = hn;
            if (wr_seq)
                seq_out[(size_t)t * (B_SZ * H_DIM) + (size_t)b * H_DIM + ep_jg] = hn;
            if (t == T_STEPS - 1)
                hlast[(size_t)b * H_DIM + ep_jg] = hn;
        }
        __syncthreads();
    }
}

// ---------------------------------------------------------------------------
// Launch: per layer — gi GEMM, h0 transpose-init, persistent recurrence.
// ---------------------------------------------------------------------------
extern "C" void kernel_launch(void* const* d_in, const int* in_sizes, int n_in,
                              void* d_out, int out_size)
{
    (void)in_sizes; (void)n_in; (void)out_size;

    const float* x    = (const float*)d_in[0];
    const float* h0   = (const float*)d_in[1];
    const float* w_ih = (const float*)d_in[2];
    const float* w_hh = (const float*)d_in[3];
    const float* b_ih = (const float*)d_in[4];
    const float* b_hh = (const float*)d_in[5];
    float* out = (float*)d_out;

    float* gi  = nullptr;
    float* seq = nullptr;
    float* hp  = nullptr;
    cudaGetSymbolAddress((void**)&gi,  g_gi);
    cudaGetSymbolAddress((void**)&seq, g_seq);
    cudaGetSymbolAddress((void**)&hp,  g_hp);

    cudaFuncSetAttribute(gru_persistent_kernel,
                         cudaFuncAttributeMaxDynamicSharedMemorySize,
                         RDYN_BYTES);

    const size_t BH = (size_t)B_SZ * H_DIM;   // 65536
    dim3 ggrid(THREE_H / BN, M_ROWS / BM);    // (24, 128)

    for (int l = 0; l < L_NUM; l++) {
        const float* A = (l == 0) ? x : seq;
        gi_gemm_kernel<<<ggrid, 256>>>(A,
                                       w_ih + (size_t)l * THREE_H * K_DIM,
                                       b_ih + (size_t)l * THREE_H,
                                       gi);
        h_init_kernel<<<256, 256>>>(h0 + (size_t)l * BH, hp);
        gru_persistent_kernel<<<NBLK, 256, RDYN_BYTES>>>(
            gi, hp,
            w_hh + (size_t)l * THREE_H * H_DIM,
            b_hh + (size_t)l * THREE_H,
            (l < L_NUM - 1) ? seq : nullptr,
            out + (size_t)l * BH);
    }
}